// round 5
// baseline (speedup 1.0000x reference)
#include <cuda_runtime.h>
#include <cuda_bf16.h>

// Problem: SpatialConsistencyLoss (fully fused single kernel)
//   original, enhanced: [32,3,512,512] f32
//   p = avg_pool4(mean_c(orig)) - avg_pool4(mean_c(enh))   [32,128,128]
//   loss[i,j] = sum over 4 dirs of (p[i,j] - p[nbr])^2, zero-padded
// Output: [32,1,128,128] f32
//
// Decomposition: 32 images x 16 strips of 8 pooled rows = 512 blocks.
// Each block computes its strip's pooled rows PLUS a 1-row halo on each
// side (10 rows x 128 cols) into smem, syncs, then emits the 8x128 loss
// tile. Out-of-image halo rows are 0, matching zero-pad conv semantics.

#define B 32
#define HP 128
#define WP 128
#define HIN 512
#define WIN 512
#define CH_STRIDE (HIN * WIN)          // 262144
#define IMG_STRIDE (3 * CH_STRIDE)     // 786432
#define STRIP_ROWS 8
#define HALO_ROWS (STRIP_ROWS + 2)     // 10
#define THREADS 256

__device__ __forceinline__ float sq(float x) { return x * x; }

__global__ __launch_bounds__(THREADS)
void scl_fused_kernel(const float* __restrict__ orig,
                      const float* __restrict__ enh,
                      float* __restrict__ out) {
    const int b     = blockIdx.x >> 4;       // image index
    const int strip = blockIdx.x & 15;       // strip within image
    const int r0    = strip * STRIP_ROWS;    // first output pooled row

    __shared__ __align__(16) float sp[HALO_ROWS * WP];   // 10*128 floats

    // ---- Phase 1: pooled difference field (incl. halo) -> smem ----
    // 1280 items, 5 per thread. Consecutive tid -> consecutive col, so the
    // float4 input loads are warp-contiguous (512B per warp per LDG.128).
#pragma unroll
    for (int k = 0; k < HALO_ROWS * WP / THREADS; ++k) {
        int it  = threadIdx.x + k * THREADS;
        int row = it >> 7;                   // 0..9
        int col = it & (WP - 1);
        int gi  = r0 - 1 + row;              // global pooled row, may be -1/128

        float v = 0.0f;
        if (gi >= 0 && gi < HP) {
            int base0 = b * IMG_STRIDE + (gi * 4) * WIN + col * 4;
            float s = 0.0f;
#pragma unroll
            for (int c = 0; c < 3; ++c) {
                int base = base0 + c * CH_STRIDE;
#pragma unroll
                for (int r = 0; r < 4; ++r) {
                    float4 ov = *reinterpret_cast<const float4*>(orig + base + r * WIN);
                    float4 ev = *reinterpret_cast<const float4*>(enh  + base + r * WIN);
                    s += (ov.x - ev.x) + (ov.y - ev.y) + (ov.z - ev.z) + (ov.w - ev.w);
                }
            }
            v = s * (1.0f / 48.0f);          // /3 channels, /16 pool
        }
        sp[it] = v;
    }
    __syncthreads();

    // ---- Phase 2: loss tile (8x128) -> gmem, one float4 per thread ----
    int row  = threadIdx.x >> 5;             // 0..7 (tile row)
    int colq = (threadIdx.x & 31) << 2;      // 0,4,...,124

    const float* ctr = &sp[(row + 1) * WP];
    float4 c  = *reinterpret_cast<const float4*>(ctr + colq);
    float4 up = *reinterpret_cast<const float4*>(&sp[row * WP] + colq);
    float4 dn = *reinterpret_cast<const float4*>(&sp[(row + 2) * WP] + colq);
    float left  = (colq > 0)      ? ctr[colq - 1] : 0.0f;
    float right = (colq < WP - 4) ? ctr[colq + 4] : 0.0f;

    float4 o;
    o.x = sq(c.x - left) + sq(c.x - c.y)   + sq(c.x - up.x) + sq(c.x - dn.x);
    o.y = sq(c.y - c.x)  + sq(c.y - c.z)   + sq(c.y - up.y) + sq(c.y - dn.y);
    o.z = sq(c.z - c.y)  + sq(c.z - c.w)   + sq(c.z - up.z) + sq(c.z - dn.z);
    o.w = sq(c.w - c.z)  + sq(c.w - right) + sq(c.w - up.w) + sq(c.w - dn.w);

    int obase = b * (HP * WP) + (r0 + row) * WP + colq;   // 16B-aligned
    *reinterpret_cast<float4*>(out + obase) = o;
}

extern "C" void kernel_launch(void* const* d_in, const int* in_sizes, int n_in,
                              void* d_out, int out_size) {
    const float* orig = (const float*)d_in[0];
    const float* enh  = (const float*)d_in[1];
    float* out = (float*)d_out;

    scl_fused_kernel<<<B * (HP / STRIP_ROWS), THREADS>>>(orig, enh, out);
}

// round 6
// speedup vs baseline: 1.0616x; 1.0616x over previous
#include <cuda_runtime.h>
#include <cuda_bf16.h>

// SpatialConsistencyLoss — single fused kernel with software grid barrier.
//   original, enhanced: [32,3,512,512] f32
//   p = avg_pool4(mean_c(orig)) - avg_pool4(mean_c(enh))   [32,128,128]
//   loss[i,j] = sum_dirs (p[i,j] - p[nbr])^2, zero-padded  -> [32,1,128,128]
//
// 512 blocks = 32 images x 16 strips of 8 pooled rows. All 512 blocks are
// co-resident (launch_bounds guarantees >=4 blocks/SM on 148 SMs = 592), so
// a counter-based grid barrier is safe. Phase 1 computes each strip's pooled
// rows exactly once (no halo recompute -> minimal DRAM traffic), phase 2
// reads only the 2 halo rows from the freshly-written L2-resident scratch.

#define B 32
#define HP 128
#define WP 128
#define NPOOL (B * HP * WP)
#define HIN 512
#define WIN 512
#define CH_STRIDE (HIN * WIN)          // 262144
#define IMG_STRIDE (3 * CH_STRIDE)     // 786432
#define STRIP_ROWS 8
#define THREADS 256
#define NBLOCKS (B * (HP / STRIP_ROWS))   // 512

__device__ float g_pooled[NPOOL];          // 2 MB scratch
__device__ unsigned int g_arrive = 0;      // grid-barrier arrive counter
__device__ unsigned int g_exit   = 0;      // grid-barrier reset counter

__device__ __forceinline__ float sq(float x) { return x * x; }

__global__ __launch_bounds__(THREADS, 4)
void scl_onepass_kernel(const float* __restrict__ orig,
                        const float* __restrict__ enh,
                        float* __restrict__ out) {
    const int b     = blockIdx.x >> 4;
    const int strip = blockIdx.x & 15;
    const int r0    = strip * STRIP_ROWS;

    __shared__ __align__(16) float sp[STRIP_ROWS * WP];   // 8*128 = 4 KB

    // ---- Phase 1: pooled diff field for this strip (no halo) ----
    // 1024 items, 4 per thread; consecutive tid -> consecutive col, so the
    // float4 input loads are warp-contiguous (512B per warp per LDG.128).
#pragma unroll
    for (int k = 0; k < STRIP_ROWS * WP / THREADS; ++k) {
        int it  = threadIdx.x + k * THREADS;
        int row = it >> 7;                  // 0..7
        int col = it & (WP - 1);
        int gi  = r0 + row;

        int base0 = b * IMG_STRIDE + (gi * 4) * WIN + col * 4;
        float s = 0.0f;
#pragma unroll
        for (int c = 0; c < 3; ++c) {
            int base = base0 + c * CH_STRIDE;
#pragma unroll
            for (int r = 0; r < 4; ++r) {
                float4 ov = *reinterpret_cast<const float4*>(orig + base + r * WIN);
                float4 ev = *reinterpret_cast<const float4*>(enh  + base + r * WIN);
                s += (ov.x - ev.x) + (ov.y - ev.y) + (ov.z - ev.z) + (ov.w - ev.w);
            }
        }
        float v = s * (1.0f / 48.0f);       // /3 channels, /16 pool
        sp[it] = v;
        g_pooled[(b << 14) + (gi << 7) + col] = v;
    }

    // ---- Grid barrier (self-resetting across graph replays) ----
    __syncthreads();
    if (threadIdx.x == 0) {
        __threadfence();                    // publish this block's g_pooled rows
        atomicAdd(&g_arrive, 1u);
        while (*(volatile unsigned int*)&g_arrive < NBLOCKS) { }
        __threadfence();                    // acquire other blocks' writes
    }
    __syncthreads();

    // ---- Phase 2: loss tile (8x128), one float4 per thread ----
    {
        int row  = threadIdx.x >> 5;        // 0..7
        int colq = (threadIdx.x & 31) << 2; // 0,4,...,124
        int gr   = r0 + row;

        const float* ctr = &sp[row << 7];
        float4 c = *reinterpret_cast<const float4*>(ctr + colq);

        float4 up;
        if (row > 0)
            up = *reinterpret_cast<const float4*>(&sp[(row - 1) << 7] + colq);
        else if (gr > 0)
            up = *reinterpret_cast<const float4*>(&g_pooled[(b << 14) + ((gr - 1) << 7) + colq]);
        else
            up = make_float4(0.f, 0.f, 0.f, 0.f);

        float4 dn;
        if (row < STRIP_ROWS - 1)
            dn = *reinterpret_cast<const float4*>(&sp[(row + 1) << 7] + colq);
        else if (gr < HP - 1)
            dn = *reinterpret_cast<const float4*>(&g_pooled[(b << 14) + ((gr + 1) << 7) + colq]);
        else
            dn = make_float4(0.f, 0.f, 0.f, 0.f);

        float left  = (colq > 0)      ? ctr[colq - 1] : 0.0f;
        float right = (colq < WP - 4) ? ctr[colq + 4] : 0.0f;

        float4 o;
        o.x = sq(c.x - left) + sq(c.x - c.y)   + sq(c.x - up.x) + sq(c.x - dn.x);
        o.y = sq(c.y - c.x)  + sq(c.y - c.z)   + sq(c.y - up.y) + sq(c.y - dn.y);
        o.z = sq(c.z - c.y)  + sq(c.z - c.w)   + sq(c.z - up.z) + sq(c.z - dn.z);
        o.w = sq(c.w - c.z)  + sq(c.w - right) + sq(c.w - up.w) + sq(c.w - dn.w);

        *reinterpret_cast<float4*>(out + (b << 14) + (gr << 7) + colq) = o;
    }

    // ---- Reset barrier counters for the next graph replay ----
    __syncthreads();
    if (threadIdx.x == 0) {
        unsigned int old = atomicAdd(&g_exit, 1u);
        if (old == NBLOCKS - 1) {           // last block out resets both
            atomicExch(&g_arrive, 0u);
            atomicExch(&g_exit, 0u);
        }
    }
}

extern "C" void kernel_launch(void* const* d_in, const int* in_sizes, int n_in,
                              void* d_out, int out_size) {
    const float* orig = (const float*)d_in[0];
    const float* enh  = (const float*)d_in[1];
    float* out = (float*)d_out;

    scl_onepass_kernel<<<NBLOCKS, THREADS>>>(orig, enh, out);
}